// round 12
// baseline (speedup 1.0000x reference)
#include <cuda_runtime.h>
#include <cuda_bf16.h>

#define BATCH 16384
#define CTX 10
#define EMB 256

// Plain 256-bit load: one LDG per lane covers a full 1KB row per warp.
__device__ __forceinline__ void ldg256(const float* p, float v[8]) {
    unsigned r0, r1, r2, r3, r4, r5, r6, r7;
    asm("ld.global.nc.v8.b32 {%0,%1,%2,%3,%4,%5,%6,%7}, [%8];"
        : "=r"(r0), "=r"(r1), "=r"(r2), "=r"(r3),
          "=r"(r4), "=r"(r5), "=r"(r6), "=r"(r7)
        : "l"(p));
    v[0] = __uint_as_float(r0); v[1] = __uint_as_float(r1);
    v[2] = __uint_as_float(r2); v[3] = __uint_as_float(r3);
    v[4] = __uint_as_float(r4); v[5] = __uint_as_float(r5);
    v[6] = __uint_as_float(r6); v[7] = __uint_as_float(r7);
}

// R8 config (one warp per (b,sign), 3-deep pipeline, 64-reg budget) with the
// single isolated change: 256-bit row loads, no cache hints.
__global__ __launch_bounds__(256, 4) void cbow_loss_kernel(
    const int* __restrict__ pos_u,
    const int* __restrict__ pos_w,
    const int* __restrict__ neg_u,
    const int* __restrict__ neg_w,
    const float* __restrict__ u_weight,
    const float* __restrict__ w_weight,
    float* __restrict__ out)
{
    const int tid = blockIdx.x * blockDim.x + threadIdx.x;
    const int warp_id = tid >> 5;
    const int lane = threadIdx.x & 31;
    const int loff = lane * 8;   // 32 bytes per lane

    int b = warp_id;
    const bool is_neg = (b >= BATCH);
    if (is_neg) b -= BATCH;

    const int* __restrict__ uidx = is_neg ? neg_u : pos_u;
    const int* __restrict__ widx = is_neg ? neg_w : pos_w;

    // w-row load issued immediately (single LDG.256 per lane)
    const long long wrow = (long long)__ldg(&widx[b]) * EMB;
    float w[8];
    ldg256(w_weight + wrow + loff, w);

    // all 10 context indices up front
    int ui[CTX];
    #pragma unroll
    for (int c = 0; c < CTX; c++)
        ui[c] = __ldg(&uidx[b * CTX + c]);

    #define UPTR(c) (u_weight + (long long)ui[(c)] * EMB + loff)

    // 3-deep pipeline: rows c, c+1 resident, c+2 prefetching
    float ra[8], rb[8];
    ldg256(UPTR(0), ra);
    ldg256(UPTR(1), rb);

    float acc = 0.0f;

    #pragma unroll
    for (int c = 0; c < CTX; c++) {
        float rn[8];
        if (c + 2 < CTX)
            ldg256(UPTR(c + 2), rn);
        #pragma unroll
        for (int i = 0; i < 8; i++)
            acc = fmaf(ra[i], w[i], acc);
        #pragma unroll
        for (int i = 0; i < 8; i++) { ra[i] = rb[i]; rb[i] = rn[i]; }
    }
    #undef UPTR

    // warp reduce
    #pragma unroll
    for (int off = 16; off > 0; off >>= 1)
        acc += __shfl_xor_sync(0xFFFFFFFFu, acc, off);

    __shared__ float warp_part[8];
    if (lane == 0) {
        float s = is_neg ? -acc : acc;
        // log_sigmoid(s) = min(s,0) - log1p(exp(-|s|))
        float ls = fminf(s, 0.0f) - log1pf(__expf(-fabsf(s)));
        warp_part[threadIdx.x >> 5] = -ls;
    }
    __syncthreads();

    if (threadIdx.x == 0) {
        float blk = 0.0f;
        #pragma unroll
        for (int w2 = 0; w2 < 8; w2++) blk += warp_part[w2];
        atomicAdd(out, blk);
    }
}

extern "C" void kernel_launch(void* const* d_in, const int* in_sizes, int n_in,
                              void* d_out, int out_size) {
    const int*   pos_u    = (const int*)d_in[0];
    const int*   pos_w    = (const int*)d_in[1];
    const int*   neg_u    = (const int*)d_in[2];
    const int*   neg_w    = (const int*)d_in[3];
    const float* u_weight = (const float*)d_in[4];
    const float* w_weight = (const float*)d_in[5];
    float* out = (float*)d_out;

    // zero the accumulator via a graph memset node (cheapest option, R8-verified)
    cudaMemsetAsync(out, 0, sizeof(float));

    const int total_warps = 2 * BATCH;
    const int blocks = total_warps / 8;  // 4096
    cbow_loss_kernel<<<blocks, 256>>>(pos_u, pos_w, neg_u, neg_w,
                                      u_weight, w_weight, out);
}